// round 8
// baseline (speedup 1.0000x reference)
#include <cuda_runtime.h>

#define NN   50000
#define NE   500000
#define HID  128
#define NGR  64
#define REP  32
#define UNB  32   // nodes per update block
#define SBLK 49   // ceil(NN/1024) scan blocks

// ---------------- device scratch (no allocations allowed) ----------------
// g_deg, g_sflag, g_gsum, g_gcnt start zero (static init) and are re-zeroed
// by their consumers each call, so every kernel_launch sees identical state.
__device__ __align__(16) float g_pa[NN*HID];        // x @ (Wn Wm_a)
__device__ __align__(16) float g_pb[NN*HID];        // x @ (Wn Wm_b)
__device__ __align__(16) float g_agg[NN*HID];       // normalized message means
__device__ __align__(16) float g_gsum[REP*NGR*HID]; // replicated graph sums
__device__ __align__(16) float g_gcnt[REP*NGR];
__device__ __align__(16) float g_WA[16*HID];        // Wn @ Wm_a
__device__ __align__(16) float g_WB[16*HID];        // Wn @ Wm_b
__device__ __align__(16) float g_WE2[8*HID];        // We @ Wm_c
__device__ __align__(16) float g_WU1[16*HID];       // Wn @ Wu_top
__device__ __align__(16) float g_bconst[HID];       // bn@Wm_a + bn@Wm_b + be@Wm_c + bm
__device__ __align__(16) float g_bup[HID];          // bn@Wu_top + bu
__device__ int  g_row[NE];
__device__ int  g_col[NE];
__device__ int  g_rank[NE];                         // within-destination rank
__device__ int2 g_epack[NE];                        // CSR payload: (src_row, edge_id)
__device__ int  g_deg[NN];
__device__ int  g_ptr[NN+1];
__device__ int  g_bsum[SBLK];
__device__ int  g_sflag[SBLK];
__device__ int  g_batchi[NN];

// ---------------- helpers ----------------
__device__ __forceinline__ void red_f32(float* p, float v) {
    asm volatile("red.global.add.f32 [%0], %1;" :: "l"(p), "f"(v) : "memory");
}
__device__ __forceinline__ unsigned long long splat2(float w) {
    unsigned long long r;
    asm("mov.b64 %0, {%1, %1};" : "=l"(r) : "r"(__float_as_uint(w)));
    return r;
}
__device__ __forceinline__ unsigned long long pack2(float a, float b) {
    unsigned long long r;
    asm("mov.b64 %0, {%1, %2};" : "=l"(r) : "r"(__float_as_uint(a)), "r"(__float_as_uint(b)));
    return r;
}
__device__ __forceinline__ void unpack2(unsigned long long v, float& a, float& b) {
    unsigned lo, hi;
    asm("mov.b64 {%0, %1}, %2;" : "=r"(lo), "=r"(hi) : "l"(v));
    a = __uint_as_float(lo); b = __uint_as_float(hi);
}
__device__ __forceinline__ void fma_f32x2(unsigned long long& d,
                                          unsigned long long a,
                                          unsigned long long b) {
    asm("fma.rn.f32x2 %0, %1, %2, %0;" : "+l"(d) : "l"(a), "l"(b));
}
__device__ __forceinline__ unsigned long long add_f32x2(unsigned long long a,
                                                        unsigned long long b) {
    unsigned long long r;
    asm("add.rn.f32x2 %0, %1, %2;" : "=l"(r) : "l"(a), "l"(b));
    return r;
}

// ---------------- 1: convert indices + histogram + rank (per-warp dtype sniff) ----------------
__global__ void k_convert(const void* __restrict__ ei, const void* __restrict__ batch) {
    int i = blockIdx.x * blockDim.x + threadIdx.x;
    const int* ei32 = (const int*)ei;
    bool active = (i < 2*NE);
    int j = (i < NE) ? i : i - NE;       // always in-bounds for both dtypes
    int hw = active ? ei32[2*j + 1] : 0;
    unsigned m = __ballot_sync(0xffffffffu, active && (hw != 0));
    const bool f64 = (m == 0u);          // int64: all odd words zero
    if (active) {
        int v = f64 ? (int)((const long long*)ei)[i] : ei32[i];
        if (i < NE) {
            g_row[i] = v;
        } else {
            int r = atomicAdd(&g_deg[v], 1);
            g_col[i - NE]  = v;
            g_rank[i - NE] = r;
        }
    }
    if (i < NN) {
        g_batchi[i] = f64 ? (int)((const long long*)batch)[i] : ((const int*)batch)[i];
    }
}

// ---------------- 2: fused exclusive scan (decoupled lookback), clears g_deg ----------------
__global__ __launch_bounds__(1024) void k_scan() {
    __shared__ int swsum[32];
    __shared__ int soff;
    int t = threadIdx.x, b = blockIdx.x;
    int idx = b * 1024 + t;
    int lane = t & 31, warp = t >> 5;
    int d = (idx < NN) ? g_deg[idx] : 0;
    if (idx < NN) g_deg[idx] = 0;            // consume-and-clear for next call

    int v = d;
    #pragma unroll
    for (int o = 1; o < 32; o <<= 1) {
        int u = __shfl_up_sync(0xffffffffu, v, o);
        if (lane >= o) v += u;
    }
    if (lane == 31) swsum[warp] = v;
    __syncthreads();
    if (warp == 0) {
        int s = swsum[lane];
        #pragma unroll
        for (int o = 1; o < 32; o <<= 1) {
            int u = __shfl_up_sync(0xffffffffu, s, o);
            if (lane >= o) s += u;
        }
        swsum[lane] = s;
    }
    __syncthreads();
    int incl = v + ((warp > 0) ? swsum[warp - 1] : 0);

    if (t == 1023) {                          // publish block total
        g_bsum[b] = incl;
        __threadfence();
        atomicExch(&g_sflag[b], 1);
    }
    if (t < 32) {                             // lookback over predecessors
        int acc = 0;
        for (int j = t; j < b; j += 32) {
            while (atomicAdd(&g_sflag[j], 0) == 0) {}
            acc += atomicAdd(&g_bsum[j], 0);
        }
        #pragma unroll
        for (int o = 16; o > 0; o >>= 1) acc += __shfl_down_sync(0xffffffffu, acc, o);
        if (t == 0) soff = acc;
    }
    __syncthreads();
    if (idx < NN) g_ptr[idx] = (incl - d) + soff;
    if (b == 0 && t == 0) g_ptr[NN] = NE;     // degree sum is NE by construction
}

// ---------------- 3: scatter edges (pure stores, no atomics), clears g_sflag ----------------
__global__ void k_scatter() {
    int i = blockIdx.x * blockDim.x + threadIdx.x;
    if (i < NE) {
        int c = g_col[i];
        g_epack[g_ptr[c] + g_rank[i]] = make_int2(g_row[i], i);
    }
    if (i < SBLK) g_sflag[i] = 0;             // consume-and-clear for next call
}

// ---------------- 4: fold weights — 57 blocks x (128,4), split-K ----------------
__global__ __launch_bounds__(512) void k_prep(
        const float* __restrict__ Wn, const float* __restrict__ bn,
        const float* __restrict__ We, const float* __restrict__ be,
        const float* __restrict__ Wm, const float* __restrict__ bm,
        const float* __restrict__ Wu, const float* __restrict__ bu) {
    __shared__ float swl[HID];
    __shared__ float sred[4][HID];
    __shared__ float sred4[4][4][HID];
    __shared__ float sbn[HID], sbe[HID];
    const int c = threadIdx.x;
    const int q = threadIdx.y;
    const int b = blockIdx.x;
    const int flat = q*HID + c;

    if (b < 56) {
        const float* Wl;
        const float* Wr;
        float* out;
        int orow;
        if (b < 48) {
            int grp = b >> 4;
            orow = b & 15;
            Wl = Wn + orow*HID;
            if      (grp == 0) { Wr = Wm;           out = g_WA;  }
            else if (grp == 1) { Wr = Wm + HID*HID; out = g_WB;  }
            else               { Wr = Wu;           out = g_WU1; }
        } else {
            orow = b - 48;
            Wl = We + orow*HID;
            Wr = Wm + 2*HID*HID;
            out = g_WE2;
        }
        if (flat < HID) swl[flat] = Wl[flat];
        __syncthreads();
        float a0 = 0.f, a1 = 0.f;
        const int k0 = 32*q;
        #pragma unroll
        for (int kk = 0; kk < 32; kk += 2) {
            a0 += swl[k0+kk]   * Wr[(k0+kk)*HID + c];
            a1 += swl[k0+kk+1] * Wr[(k0+kk+1)*HID + c];
        }
        sred[q][c] = a0 + a1;
        __syncthreads();
        if (q == 0)
            out[orow*HID + c] = (sred[0][c] + sred[1][c]) + (sred[2][c] + sred[3][c]);
    } else {
        if (flat < HID) { sbn[flat] = bn[flat]; sbe[flat] = be[flat]; }
        __syncthreads();
        float p0 = 0.f, p1 = 0.f, p2 = 0.f, p3 = 0.f;
        const int k0 = 32*q;
        #pragma unroll
        for (int kk = 0; kk < 32; kk++) {
            int k = k0 + kk;
            float bnk = sbn[k];
            p0 += bnk    * Wm[k*HID + c];
            p1 += bnk    * Wm[(HID + k)*HID + c];
            p2 += sbe[k] * Wm[(2*HID + k)*HID + c];
            p3 += bnk    * Wu[k*HID + c];
        }
        sred4[q][0][c] = p0; sred4[q][1][c] = p1;
        sred4[q][2][c] = p2; sred4[q][3][c] = p3;
        __syncthreads();
        if (q == 0) {
            float b0 = sred4[0][0][c]+sred4[1][0][c]+sred4[2][0][c]+sred4[3][0][c];
            float b1 = sred4[0][1][c]+sred4[1][1][c]+sred4[2][1][c]+sred4[3][1][c];
            float b2 = sred4[0][2][c]+sred4[1][2][c]+sred4[2][2][c]+sred4[3][2][c];
            float u0 = sred4[0][3][c]+sred4[1][3][c]+sred4[2][3][c]+sred4[3][3][c];
            g_bconst[c] = bm[c] + b0 + b1 + b2;
            g_bup[c]    = bu[c] + u0;
        }
    }
}

// ---------------- 5: per-node projections pa, pb ----------------
__global__ __launch_bounds__(256) void k_node(const float* __restrict__ x) {
    __shared__ float4 sWA[16*32], sWB[16*32];
    int t = threadIdx.x;
    for (int j = t; j < 16*32; j += 256) {
        sWA[j] = ((const float4*)g_WA)[j];
        sWB[j] = ((const float4*)g_WB)[j];
    }
    __syncthreads();
    int warp = t >> 5, lane = t & 31;
    int n = blockIdx.x * 8 + warp;
    if (n >= NN) return;
    const float4* xr = (const float4*)(x + n*16);
    float xv[16];
    #pragma unroll
    for (int q = 0; q < 4; q++) {
        float4 v = xr[q];
        xv[4*q+0] = v.x; xv[4*q+1] = v.y; xv[4*q+2] = v.z; xv[4*q+3] = v.w;
    }
    float4 a = {0,0,0,0}, b = {0,0,0,0};
    #pragma unroll
    for (int i = 0; i < 16; i++) {
        float4 wa = sWA[i*32 + lane];
        float4 wb = sWB[i*32 + lane];
        a.x += xv[i]*wa.x; a.y += xv[i]*wa.y; a.z += xv[i]*wa.z; a.w += xv[i]*wa.w;
        b.x += xv[i]*wb.x; b.y += xv[i]*wb.y; b.z += xv[i]*wb.z; b.w += xv[i]*wb.w;
    }
    ((float4*)g_pa)[n*32 + lane] = a;
    ((float4*)g_pb)[n*32 + lane] = b;
}

// ---------------- 6: CSR aggregation — one warp per node, 2-edge unroll ----------------
__device__ __forceinline__ void agg_edge(int2 e, int lane,
                                         const float* __restrict__ ea,
                                         const ulonglong2* __restrict__ sWE,
                                         unsigned long long bx0, unsigned long long bx1,
                                         float4& acc) {
    ulonglong2 pav = ((const ulonglong2*)g_pa)[e.x*32 + lane];
    const float4* eap = (const float4*)(ea + (long long)e.y*8);
    float4 A = eap[0];                 // broadcast loads (all lanes same addr)
    float4 B = eap[1];
    unsigned long long m0 = add_f32x2(pav.x, bx0);
    unsigned long long m1 = add_f32x2(pav.y, bx1);
    float ej[8] = {A.x, A.y, A.z, A.w, B.x, B.y, B.z, B.w};
    #pragma unroll
    for (int j = 0; j < 8; j++) {
        unsigned long long ej2 = splat2(ej[j]);
        ulonglong2 w = sWE[j*32 + lane];
        fma_f32x2(m0, ej2, w.x);
        fma_f32x2(m1, ej2, w.y);
    }
    float f0, f1, f2, f3;
    unpack2(m0, f0, f1);
    unpack2(m1, f2, f3);
    acc.x += fmaxf(f0, 0.f);
    acc.y += fmaxf(f1, 0.f);
    acc.z += fmaxf(f2, 0.f);
    acc.w += fmaxf(f3, 0.f);
}

__global__ __launch_bounds__(256) void k_agg(const float* __restrict__ ea) {
    __shared__ ulonglong2 sWE[8*32];
    __shared__ float4 sbc[32];
    int t = threadIdx.x;
    sWE[t] = ((const ulonglong2*)g_WE2)[t];
    if (t < 32) sbc[t] = ((const float4*)g_bconst)[t];
    __syncthreads();

    int warp = t >> 5, lane = t & 31;
    int node = blockIdx.x * 8 + warp;
    if (node >= NN) return;
    int beg = g_ptr[node];
    int end = g_ptr[node + 1];

    float4 pbv = ((const float4*)g_pb)[node*32 + lane];
    float4 bc  = sbc[lane];
    unsigned long long bx0 = pack2(pbv.x + bc.x, pbv.y + bc.y);
    unsigned long long bx1 = pack2(pbv.z + bc.z, pbv.w + bc.w);

    float4 acc0 = {0.f,0.f,0.f,0.f};
    float4 acc1 = {0.f,0.f,0.f,0.f};
    int p = beg;
    for (; p + 2 <= end; p += 2) {
        int2 e0 = g_epack[p];
        int2 e1 = g_epack[p + 1];
        agg_edge(e0, lane, ea, sWE, bx0, bx1, acc0);
        agg_edge(e1, lane, ea, sWE, bx0, bx1, acc1);
    }
    if (p < end) {
        int2 e0 = g_epack[p];
        agg_edge(e0, lane, ea, sWE, bx0, bx1, acc0);
    }
    float4 acc = {acc0.x + acc1.x, acc0.y + acc1.y, acc0.z + acc1.z, acc0.w + acc1.w};
    float inv = 1.f / fmaxf((float)(end - beg), 1.f);
    acc.x *= inv; acc.y *= inv; acc.z *= inv; acc.w *= inv;
    ((float4*)g_agg)[node*32 + lane] = acc;
}

// ---------------- 7: node update + graph pooling (LDS.128 tiles) ----------------
__global__ __launch_bounds__(128) void k_update(const float* __restrict__ x,
                                                const float* __restrict__ Wu) {
    __shared__ __align__(16) float saggT[HID][UNB + 4];   // 144B rows, 16B aligned
    __shared__ __align__(16) float sxT[16][UNB + 4];
    __shared__ int sbatch[UNB];
    int t  = threadIdx.x;                   // thread = channel c
    int n0 = blockIdx.x * UNB;

    if (t < UNB) {
        int node = n0 + t;
        sbatch[t] = (node < NN) ? g_batchi[node] : 0;
    }
    for (int n = 0; n < UNB; n++) {
        int node = n0 + n;
        saggT[t][n] = (node < NN) ? g_agg[node*HID + t] : 0.f;
    }
    for (int idx = t; idx < 16*UNB; idx += 128) {
        int n = idx & 31, i = idx >> 5;
        int node = n0 + n;
        sxT[i][n] = (node < NN) ? x[node*16 + i] : 0.f;
    }
    __syncthreads();

    const int c = t;
    unsigned long long acc2[UNB/2];
    #pragma unroll
    for (int p = 0; p < UNB/2; p++) acc2[p] = 0ULL;

    #pragma unroll
    for (int i = 0; i < 16; i++) {
        unsigned long long w2 = splat2(g_WU1[i*HID + c]);
        const ulonglong2* srow = (const ulonglong2*)&sxT[i][0];
        #pragma unroll
        for (int q = 0; q < UNB/4; q++) {
            ulonglong2 a = srow[q];
            fma_f32x2(acc2[2*q],   a.x, w2);
            fma_f32x2(acc2[2*q+1], a.y, w2);
        }
    }
    for (int k = 0; k < HID; k++) {
        unsigned long long w2 = splat2(Wu[(HID + k)*HID + c]);   // Wu_bot
        const ulonglong2* srow = (const ulonglong2*)&saggT[k][0];
        #pragma unroll
        for (int q = 0; q < UNB/4; q++) {
            ulonglong2 a = srow[q];
            fma_f32x2(acc2[2*q],   a.x, w2);
            fma_f32x2(acc2[2*q+1], a.y, w2);
        }
    }

    float bupv = g_bup[c];
    int   rep  = blockIdx.x & (REP - 1);
    float* gsbase = &g_gsum[rep*NGR*HID];
    int   cur = sbatch[0];
    float sum = 0.f;
    #pragma unroll
    for (int p = 0; p < UNB/2; p++) {
        float hv[2];
        unpack2(acc2[p], hv[0], hv[1]);
        #pragma unroll
        for (int q = 0; q < 2; q++) {
            int n = 2*p + q;
            int node = n0 + n;
            if (node < NN) {
                float h = fmaxf(hv[q] + bupv, 0.f);
                int b = sbatch[n];
                if (b != cur) {
                    red_f32(gsbase + cur*HID + c, sum);
                    cur = b; sum = 0.f;
                }
                sum += h;
            }
        }
    }
    red_f32(gsbase + cur*HID + c, sum);

    if (t < UNB) {
        int node = n0 + t;
        if (node < NN) red_f32(&g_gcnt[rep*NGR + sbatch[t]], 1.0f);
    }
}

// ---------------- 8: readout MLP, clears g_gsum/g_gcnt ----------------
__global__ __launch_bounds__(128) void k_final(const float* __restrict__ Wr1,
                                               const float* __restrict__ br1,
                                               const float* __restrict__ Wr2,
                                               const float* __restrict__ br2,
                                               float* __restrict__ out) {
    __shared__ float sg[HID];
    __shared__ float sred[4];
    int g = blockIdx.x, t = threadIdx.x;
    float s = 0.f;
    for (int r = 0; r < REP; r++) s += g_gsum[r*NGR*HID + g*HID + t];
    float gc = 0.f;
    for (int r = 0; r < REP; r++) gc += g_gcnt[r*NGR + g];
    sg[t] = s / fmaxf(gc, 1.f);
    __syncthreads();
    // consume-and-clear (this block owns graph g's slots)
    for (int r = 0; r < REP; r++) g_gsum[r*NGR*HID + g*HID + t] = 0.f;
    if (t == 0) for (int r = 0; r < REP; r++) g_gcnt[r*NGR + g] = 0.f;

    float acc = br1[t];
    for (int k = 0; k < HID; k++) acc += sg[k] * Wr1[k*HID + t];
    acc = fmaxf(acc, 0.f);
    float v = acc * Wr2[t];
    #pragma unroll
    for (int o = 16; o > 0; o >>= 1) v += __shfl_down_sync(0xffffffffu, v, o);
    if ((t & 31) == 0) sred[t >> 5] = v;
    __syncthreads();
    if (t == 0) out[g] = sred[0] + sred[1] + sred[2] + sred[3] + br2[0];
}

// ---------------- launch ----------------
extern "C" void kernel_launch(void* const* d_in, const int* in_sizes, int n_in,
                              void* d_out, int out_size) {
    const float* x     = (const float*)d_in[0];
    const float* ea    = (const float*)d_in[1];
    const void*  ei    = d_in[2];
    const void*  batch = d_in[3];
    const float* Wn  = (const float*)d_in[4];
    const float* bn  = (const float*)d_in[5];
    const float* We  = (const float*)d_in[6];
    const float* be  = (const float*)d_in[7];
    const float* Wm  = (const float*)d_in[8];
    const float* bm  = (const float*)d_in[9];
    const float* Wu  = (const float*)d_in[10];
    const float* bu  = (const float*)d_in[11];
    const float* Wr1 = (const float*)d_in[12];
    const float* br1 = (const float*)d_in[13];
    const float* Wr2 = (const float*)d_in[14];
    const float* br2 = (const float*)d_in[15];
    float* out = (float*)d_out;

    k_prep    <<<57, dim3(128,4)>>>(Wn, bn, We, be, Wm, bm, Wu, bu);
    k_convert <<<(2*NE + 255)/256, 256>>>(ei, batch);
    k_scan    <<<SBLK, 1024>>>();
    k_scatter <<<(NE + 255)/256, 256>>>();     // launch #4 -> profiled
    k_node    <<<(NN + 7)/8, 256>>>(x);
    k_agg     <<<(NN + 7)/8, 256>>>(ea);
    k_update  <<<(NN + UNB - 1)/UNB, 128>>>(x, Wu);
    k_final   <<<NGR, 128>>>(Wr1, br1, Wr2, br2, out);
}

// round 9
// speedup vs baseline: 1.0426x; 1.0426x over previous
#include <cuda_runtime.h>

#define NN   50000
#define NE   500000
#define HID  128
#define NGR  64
#define REP  32
#define UNB  32   // nodes per update block
#define SBLK 49   // ceil(NN/1024) scan blocks

// ---------------- device scratch (no allocations allowed) ----------------
// g_deg, g_gsum, g_gcnt start zero (static init) and are re-zeroed by their
// consumers each call, so every kernel_launch sees identical state.
__device__ __align__(16) float g_pa[NN*HID];        // x @ (Wn Wm_a)
__device__ __align__(16) float g_pb[NN*HID];        // x @ (Wn Wm_b)
__device__ __align__(16) float g_agg[NN*HID];       // normalized message means
__device__ __align__(16) float g_gsum[REP*NGR*HID]; // replicated graph sums
__device__ __align__(16) float g_gcnt[REP*NGR];
__device__ __align__(16) float g_WA[16*HID];        // Wn @ Wm_a
__device__ __align__(16) float g_WB[16*HID];        // Wn @ Wm_b
__device__ __align__(16) float g_WE2[8*HID];        // We @ Wm_c
__device__ __align__(16) float g_WU1[16*HID];       // Wn @ Wu_top
__device__ __align__(16) float g_bconst[HID];       // bn@Wm_a + bn@Wm_b + be@Wm_c + bm
__device__ __align__(16) float g_bup[HID];          // bn@Wu_top + bu
__device__ int  g_row[NE];
__device__ int  g_col[NE];
__device__ int  g_rank[NE];                         // within-destination rank
__device__ int2 g_epack[NE];                        // CSR payload: (src_row, edge_id)
__device__ int  g_deg[NN];
__device__ int  g_ptr[NN+1];
__device__ int  g_bsum[SBLK];
__device__ int  g_batchi[NN];

// ---------------- helpers ----------------
__device__ __forceinline__ void red_f32(float* p, float v) {
    asm volatile("red.global.add.f32 [%0], %1;" :: "l"(p), "f"(v) : "memory");
}
__device__ __forceinline__ unsigned long long splat2(float w) {
    unsigned long long r;
    asm("mov.b64 %0, {%1, %1};" : "=l"(r) : "r"(__float_as_uint(w)));
    return r;
}
__device__ __forceinline__ unsigned long long pack2(float a, float b) {
    unsigned long long r;
    asm("mov.b64 %0, {%1, %2};" : "=l"(r) : "r"(__float_as_uint(a)), "r"(__float_as_uint(b)));
    return r;
}
__device__ __forceinline__ void unpack2(unsigned long long v, float& a, float& b) {
    unsigned lo, hi;
    asm("mov.b64 {%0, %1}, %2;" : "=r"(lo), "=r"(hi) : "l"(v));
    a = __uint_as_float(lo); b = __uint_as_float(hi);
}
__device__ __forceinline__ void fma_f32x2(unsigned long long& d,
                                          unsigned long long a,
                                          unsigned long long b) {
    asm("fma.rn.f32x2 %0, %1, %2, %0;" : "+l"(d) : "l"(a), "l"(b));
}
__device__ __forceinline__ unsigned long long add_f32x2(unsigned long long a,
                                                        unsigned long long b) {
    unsigned long long r;
    asm("add.rn.f32x2 %0, %1, %2;" : "=l"(r) : "l"(a), "l"(b));
    return r;
}

// ---------------- 1: convert indices + histogram + rank (per-warp dtype sniff) ----------------
__global__ void k_convert(const void* __restrict__ ei, const void* __restrict__ batch) {
    int i = blockIdx.x * blockDim.x + threadIdx.x;
    const int* ei32 = (const int*)ei;
    bool active = (i < 2*NE);
    int j = (i < NE) ? i : i - NE;       // always in-bounds for both dtypes
    int hw = active ? ei32[2*j + 1] : 0;
    unsigned m = __ballot_sync(0xffffffffu, active && (hw != 0));
    const bool f64 = (m == 0u);          // int64: all odd words zero
    if (active) {
        int v = f64 ? (int)((const long long*)ei)[i] : ei32[i];
        if (i < NE) {
            g_row[i] = v;
        } else {
            int r = atomicAdd(&g_deg[v], 1);
            g_col[i - NE]  = v;
            g_rank[i - NE] = r;
        }
    }
    if (i < NN) {
        g_batchi[i] = f64 ? (int)((const long long*)batch)[i] : ((const int*)batch)[i];
    }
}

// ---------------- 2a: per-block inclusive scan of degrees (clears g_deg) ----------------
__global__ __launch_bounds__(1024) void k_scan1() {
    __shared__ int swsum[32];
    int t   = threadIdx.x;
    int idx = blockIdx.x * 1024 + t;
    int lane = t & 31, warp = t >> 5;
    int d = (idx < NN) ? g_deg[idx] : 0;
    if (idx < NN) g_deg[idx] = 0;            // consume-and-clear for next call

    int v = d;
    #pragma unroll
    for (int o = 1; o < 32; o <<= 1) {
        int u = __shfl_up_sync(0xffffffffu, v, o);
        if (lane >= o) v += u;
    }
    if (lane == 31) swsum[warp] = v;
    __syncthreads();
    if (warp == 0) {
        int s = swsum[lane];
        #pragma unroll
        for (int o = 1; o < 32; o <<= 1) {
            int u = __shfl_up_sync(0xffffffffu, s, o);
            if (lane >= o) s += u;
        }
        swsum[lane] = s;
    }
    __syncthreads();
    int incl = v + ((warp > 0) ? swsum[warp - 1] : 0);
    if (idx < NN) g_ptr[idx] = incl - d;     // within-block exclusive prefix
    if (t == 1023) g_bsum[blockIdx.x] = incl;
}

// ---------------- 2b: add block offsets (each block reduces bsum itself) ----------------
__global__ __launch_bounds__(1024) void k_scan3() {
    __shared__ int soff;
    int t = threadIdx.x;
    if (t < 32) {
        int b = blockIdx.x;
        int v = 0;
        if (t      < b) v += g_bsum[t];
        if (t + 32 < b) v += g_bsum[t + 32];
        #pragma unroll
        for (int o = 16; o > 0; o >>= 1) v += __shfl_down_sync(0xffffffffu, v, o);
        if (t == 0) soff = v;
    }
    __syncthreads();
    int idx = blockIdx.x * 1024 + t;
    if (idx < NN) g_ptr[idx] += soff;
    if (blockIdx.x == 0 && t == 0) g_ptr[NN] = NE;   // degree sum is NE
}

// ---------------- 3: scatter edges (pure stores, no atomics) ----------------
__global__ void k_scatter() {
    int i = blockIdx.x * blockDim.x + threadIdx.x;
    if (i < NE) {
        int c = g_col[i];
        g_epack[g_ptr[c] + g_rank[i]] = make_int2(g_row[i], i);
    }
}

// ---------------- 4: fold weights — 57 blocks x (128,4), split-K ----------------
__global__ __launch_bounds__(512) void k_prep(
        const float* __restrict__ Wn, const float* __restrict__ bn,
        const float* __restrict__ We, const float* __restrict__ be,
        const float* __restrict__ Wm, const float* __restrict__ bm,
        const float* __restrict__ Wu, const float* __restrict__ bu) {
    __shared__ float swl[HID];
    __shared__ float sred[4][HID];
    __shared__ float sred4[4][4][HID];
    __shared__ float sbn[HID], sbe[HID];
    const int c = threadIdx.x;
    const int q = threadIdx.y;
    const int b = blockIdx.x;
    const int flat = q*HID + c;

    if (b < 56) {
        const float* Wl;
        const float* Wr;
        float* out;
        int orow;
        if (b < 48) {
            int grp = b >> 4;
            orow = b & 15;
            Wl = Wn + orow*HID;
            if      (grp == 0) { Wr = Wm;           out = g_WA;  }
            else if (grp == 1) { Wr = Wm + HID*HID; out = g_WB;  }
            else               { Wr = Wu;           out = g_WU1; }
        } else {
            orow = b - 48;
            Wl = We + orow*HID;
            Wr = Wm + 2*HID*HID;
            out = g_WE2;
        }
        if (flat < HID) swl[flat] = Wl[flat];
        __syncthreads();
        float a0 = 0.f, a1 = 0.f;
        const int k0 = 32*q;
        #pragma unroll
        for (int kk = 0; kk < 32; kk += 2) {
            a0 += swl[k0+kk]   * Wr[(k0+kk)*HID + c];
            a1 += swl[k0+kk+1] * Wr[(k0+kk+1)*HID + c];
        }
        sred[q][c] = a0 + a1;
        __syncthreads();
        if (q == 0)
            out[orow*HID + c] = (sred[0][c] + sred[1][c]) + (sred[2][c] + sred[3][c]);
    } else {
        if (flat < HID) { sbn[flat] = bn[flat]; sbe[flat] = be[flat]; }
        __syncthreads();
        float p0 = 0.f, p1 = 0.f, p2 = 0.f, p3 = 0.f;
        const int k0 = 32*q;
        #pragma unroll
        for (int kk = 0; kk < 32; kk++) {
            int k = k0 + kk;
            float bnk = sbn[k];
            p0 += bnk    * Wm[k*HID + c];
            p1 += bnk    * Wm[(HID + k)*HID + c];
            p2 += sbe[k] * Wm[(2*HID + k)*HID + c];
            p3 += bnk    * Wu[k*HID + c];
        }
        sred4[q][0][c] = p0; sred4[q][1][c] = p1;
        sred4[q][2][c] = p2; sred4[q][3][c] = p3;
        __syncthreads();
        if (q == 0) {
            float b0 = sred4[0][0][c]+sred4[1][0][c]+sred4[2][0][c]+sred4[3][0][c];
            float b1 = sred4[0][1][c]+sred4[1][1][c]+sred4[2][1][c]+sred4[3][1][c];
            float b2 = sred4[0][2][c]+sred4[1][2][c]+sred4[2][2][c]+sred4[3][2][c];
            float u0 = sred4[0][3][c]+sred4[1][3][c]+sred4[2][3][c]+sred4[3][3][c];
            g_bconst[c] = bm[c] + b0 + b1 + b2;
            g_bup[c]    = bu[c] + u0;
        }
    }
}

// ---------------- 5: per-node projections pa, pb ----------------
__global__ __launch_bounds__(256) void k_node(const float* __restrict__ x) {
    __shared__ float4 sWA[16*32], sWB[16*32];
    int t = threadIdx.x;
    for (int j = t; j < 16*32; j += 256) {
        sWA[j] = ((const float4*)g_WA)[j];
        sWB[j] = ((const float4*)g_WB)[j];
    }
    __syncthreads();
    int warp = t >> 5, lane = t & 31;
    int n = blockIdx.x * 8 + warp;
    if (n >= NN) return;
    const float4* xr = (const float4*)(x + n*16);
    float xv[16];
    #pragma unroll
    for (int q = 0; q < 4; q++) {
        float4 v = xr[q];
        xv[4*q+0] = v.x; xv[4*q+1] = v.y; xv[4*q+2] = v.z; xv[4*q+3] = v.w;
    }
    float4 a = {0,0,0,0}, b = {0,0,0,0};
    #pragma unroll
    for (int i = 0; i < 16; i++) {
        float4 wa = sWA[i*32 + lane];
        float4 wb = sWB[i*32 + lane];
        a.x += xv[i]*wa.x; a.y += xv[i]*wa.y; a.z += xv[i]*wa.z; a.w += xv[i]*wa.w;
        b.x += xv[i]*wb.x; b.y += xv[i]*wb.y; b.z += xv[i]*wb.z; b.w += xv[i]*wb.w;
    }
    ((float4*)g_pa)[n*32 + lane] = a;
    ((float4*)g_pb)[n*32 + lane] = b;
}

// ---------------- 6: CSR aggregation — weights in REGISTERS, pipelined gathers ----------------
__global__ __launch_bounds__(256) void k_agg(const float* __restrict__ ea) {
    __shared__ float4 sbc[32];
    int t = threadIdx.x;
    int warp = t >> 5, lane = t & 31;

    // Per-lane weight slice WE2[j][4*lane .. 4*lane+3] in registers (zero LDS in loop)
    unsigned long long wx[8], wy[8];
    #pragma unroll
    for (int j = 0; j < 8; j++) {
        ulonglong2 w = ((const ulonglong2*)g_WE2)[j*32 + lane];
        wx[j] = w.x; wy[j] = w.y;
    }
    if (t < 32) sbc[t] = ((const float4*)g_bconst)[t];
    __syncthreads();

    int node = blockIdx.x * 8 + warp;
    if (node >= NN) return;
    int beg = g_ptr[node];
    int end = g_ptr[node + 1];

    float4 pbv = ((const float4*)g_pb)[node*32 + lane];
    float4 bc  = sbc[lane];
    unsigned long long bx0 = pack2(pbv.x + bc.x, pbv.y + bc.y);
    unsigned long long bx1 = pack2(pbv.z + bc.z, pbv.w + bc.w);

    float4 acc = {0.f, 0.f, 0.f, 0.f};
    // pipeline: epack prefetched 2 ahead, pa/ea 1 ahead
    int2 e1 = {0,0}, e2 = {0,0};
    ulonglong2 pav = {0ULL, 0ULL};
    float4 A = {0,0,0,0}, B = {0,0,0,0};
    if (beg < end)     e1 = g_epack[beg];
    if (beg + 1 < end) e2 = g_epack[beg + 1];
    if (beg < end) {
        pav = ((const ulonglong2*)g_pa)[e1.x*32 + lane];
        const float4* eap = (const float4*)(ea + (long long)e1.y*8);
        A = eap[0]; B = eap[1];
    }
    for (int p = beg; p < end; p++) {
        ulonglong2 pc = pav;
        float4 Ac = A, Bc = B;
        e1 = e2;
        if (p + 2 < end) e2 = g_epack[p + 2];
        if (p + 1 < end) {
            pav = ((const ulonglong2*)g_pa)[e1.x*32 + lane];
            const float4* eap = (const float4*)(ea + (long long)e1.y*8);
            A = eap[0]; B = eap[1];
        }
        unsigned long long m0 = add_f32x2(pc.x, bx0);
        unsigned long long m1 = add_f32x2(pc.y, bx1);
        float ej[8] = {Ac.x, Ac.y, Ac.z, Ac.w, Bc.x, Bc.y, Bc.z, Bc.w};
        #pragma unroll
        for (int j = 0; j < 8; j++) {
            unsigned long long ej2 = splat2(ej[j]);
            fma_f32x2(m0, ej2, wx[j]);
            fma_f32x2(m1, ej2, wy[j]);
        }
        float f0, f1, f2, f3;
        unpack2(m0, f0, f1);
        unpack2(m1, f2, f3);
        acc.x += fmaxf(f0, 0.f);
        acc.y += fmaxf(f1, 0.f);
        acc.z += fmaxf(f2, 0.f);
        acc.w += fmaxf(f3, 0.f);
    }
    float inv = 1.f / fmaxf((float)(end - beg), 1.f);
    acc.x *= inv; acc.y *= inv; acc.z *= inv; acc.w *= inv;
    ((float4*)g_agg)[node*32 + lane] = acc;
}

// ---------------- 7: node update + graph pooling ----------------
__global__ __launch_bounds__(128) void k_update(const float* __restrict__ x,
                                                const float* __restrict__ Wu) {
    __shared__ __align__(16) float saggT[HID][UNB + 4];   // 144B rows, 16B aligned
    __shared__ __align__(16) float sxT[16][UNB + 4];
    __shared__ int sbatch[UNB];
    int t  = threadIdx.x;                   // thread = channel c
    int n0 = blockIdx.x * UNB;

    if (t < UNB) {
        int node = n0 + t;
        sbatch[t] = (node < NN) ? g_batchi[node] : 0;
    }
    for (int n = 0; n < UNB; n++) {
        int node = n0 + n;
        saggT[t][n] = (node < NN) ? g_agg[node*HID + t] : 0.f;
    }
    for (int idx = t; idx < 16*UNB; idx += 128) {
        int n = idx & 31, i = idx >> 5;
        int node = n0 + n;
        sxT[i][n] = (node < NN) ? x[node*16 + i] : 0.f;
    }
    __syncthreads();

    const int c = t;
    unsigned long long acc2[UNB/2];
    #pragma unroll
    for (int p = 0; p < UNB/2; p++) acc2[p] = 0ULL;

    #pragma unroll
    for (int i = 0; i < 16; i++) {
        unsigned long long w2 = splat2(g_WU1[i*HID + c]);
        const ulonglong2* srow = (const ulonglong2*)&sxT[i][0];
        #pragma unroll
        for (int q = 0; q < UNB/4; q++) {
            ulonglong2 a = srow[q];
            fma_f32x2(acc2[2*q],   a.x, w2);
            fma_f32x2(acc2[2*q+1], a.y, w2);
        }
    }
    for (int k = 0; k < HID; k++) {
        unsigned long long w2 = splat2(Wu[(HID + k)*HID + c]);   // Wu_bot
        const ulonglong2* srow = (const ulonglong2*)&saggT[k][0];
        #pragma unroll
        for (int q = 0; q < UNB/4; q++) {
            ulonglong2 a = srow[q];
            fma_f32x2(acc2[2*q],   a.x, w2);
            fma_f32x2(acc2[2*q+1], a.y, w2);
        }
    }

    float bupv = g_bup[c];
    int   rep  = blockIdx.x & (REP - 1);
    float* gsbase = &g_gsum[rep*NGR*HID];
    int   cur = sbatch[0];
    float sum = 0.f;
    #pragma unroll
    for (int p = 0; p < UNB/2; p++) {
        float hv[2];
        unpack2(acc2[p], hv[0], hv[1]);
        #pragma unroll
        for (int q = 0; q < 2; q++) {
            int n = 2*p + q;
            int node = n0 + n;
            if (node < NN) {
                float h = fmaxf(hv[q] + bupv, 0.f);
                int b = sbatch[n];
                if (b != cur) {
                    red_f32(gsbase + cur*HID + c, sum);
                    cur = b; sum = 0.f;
                }
                sum += h;
            }
        }
    }
    red_f32(gsbase + cur*HID + c, sum);

    if (t < UNB) {
        int node = n0 + t;
        if (node < NN) red_f32(&g_gcnt[rep*NGR + sbatch[t]], 1.0f);
    }
}

// ---------------- 8: readout MLP, clears g_gsum/g_gcnt ----------------
__global__ __launch_bounds__(128) void k_final(const float* __restrict__ Wr1,
                                               const float* __restrict__ br1,
                                               const float* __restrict__ Wr2,
                                               const float* __restrict__ br2,
                                               float* __restrict__ out) {
    __shared__ float sg[HID];
    __shared__ float sred[4];
    int g = blockIdx.x, t = threadIdx.x;
    float s = 0.f;
    for (int r = 0; r < REP; r++) s += g_gsum[r*NGR*HID + g*HID + t];
    float gc = 0.f;
    for (int r = 0; r < REP; r++) gc += g_gcnt[r*NGR + g];
    sg[t] = s / fmaxf(gc, 1.f);
    __syncthreads();
    // consume-and-clear (this block owns graph g's slots)
    for (int r = 0; r < REP; r++) g_gsum[r*NGR*HID + g*HID + t] = 0.f;
    if (t == 0) for (int r = 0; r < REP; r++) g_gcnt[r*NGR + g] = 0.f;

    float acc = br1[t];
    for (int k = 0; k < HID; k++) acc += sg[k] * Wr1[k*HID + t];
    acc = fmaxf(acc, 0.f);
    float v = acc * Wr2[t];
    #pragma unroll
    for (int o = 16; o > 0; o >>= 1) v += __shfl_down_sync(0xffffffffu, v, o);
    if ((t & 31) == 0) sred[t >> 5] = v;
    __syncthreads();
    if (t == 0) out[g] = sred[0] + sred[1] + sred[2] + sred[3] + br2[0];
}

// ---------------- launch ----------------
extern "C" void kernel_launch(void* const* d_in, const int* in_sizes, int n_in,
                              void* d_out, int out_size) {
    const float* x     = (const float*)d_in[0];
    const float* ea    = (const float*)d_in[1];
    const void*  ei    = d_in[2];
    const void*  batch = d_in[3];
    const float* Wn  = (const float*)d_in[4];
    const float* bn  = (const float*)d_in[5];
    const float* We  = (const float*)d_in[6];
    const float* be  = (const float*)d_in[7];
    const float* Wm  = (const float*)d_in[8];
    const float* bm  = (const float*)d_in[9];
    const float* Wu  = (const float*)d_in[10];
    const float* bu  = (const float*)d_in[11];
    const float* Wr1 = (const float*)d_in[12];
    const float* br1 = (const float*)d_in[13];
    const float* Wr2 = (const float*)d_in[14];
    const float* br2 = (const float*)d_in[15];
    float* out = (float*)d_out;

    k_prep    <<<57, dim3(128,4)>>>(Wn, bn, We, be, Wm, bm, Wu, bu);
    k_convert <<<(2*NE + 255)/256, 256>>>(ei, batch);
    k_scan1   <<<SBLK, 1024>>>();
    k_node    <<<(NN + 7)/8, 256>>>(x);        // launch #4 -> profiled
    k_scan3   <<<SBLK, 1024>>>();
    k_scatter <<<(NE + 255)/256, 256>>>();
    k_agg     <<<(NN + 7)/8, 256>>>(ea);
    k_update  <<<(NN + UNB - 1)/UNB, 128>>>(x, Wu);
    k_final   <<<NGR, 128>>>(Wr1, br1, Wr2, br2, out);
}

// round 10
// speedup vs baseline: 1.1739x; 1.1259x over previous
#include <cuda_runtime.h>

#define NN   50000
#define NE   500000
#define HID  128
#define NGR  64
#define REP  32
#define UNB  32    // nodes per update block
#define SBLK 49    // ceil(NN/1024) scan blocks
#define NBN  1563  // ceil(NN/32) node blocks
#define NBC  1954  // ceil(2*NE/512) convert blocks
#define NBS  1954  // ceil(NE/256) scatter blocks

// ---------------- device scratch (no allocations allowed) ----------------
// g_deg, g_sflag, g_gsum, g_gcnt start zero (static init) and are re-zeroed
// by their consumers each call, so every kernel_launch sees identical state.
__device__ __align__(16) float g_pa[NN*HID];        // x @ (Wn Wm_a)
__device__ __align__(16) float g_pb[NN*HID];        // x @ (Wn Wm_b)
__device__ __align__(16) float g_agg[NN*HID];       // normalized message means
__device__ __align__(16) float g_gsum[REP*NGR*HID]; // replicated graph sums
__device__ __align__(16) float g_gcnt[REP*NGR];
__device__ __align__(16) float g_WA[16*HID];        // Wn @ Wm_a
__device__ __align__(16) float g_WB[16*HID];        // Wn @ Wm_b
__device__ __align__(16) float g_WE2[8*HID];        // We @ Wm_c
__device__ __align__(16) float g_WU1[16*HID];       // Wn @ Wu_top
__device__ __align__(16) float g_bconst[HID];       // bn@Wm_a + bn@Wm_b + be@Wm_c + bm
__device__ __align__(16) float g_bup[HID];          // bn@Wu_top + bu
__device__ int  g_row[NE];
__device__ int  g_col[NE];
__device__ int  g_rank[NE];                         // within-destination rank
__device__ int2 g_epack[NE];                        // CSR payload: (src_row, edge_id)
__device__ int  g_deg[NN];
__device__ int  g_ptr[NN+1];
__device__ int  g_bsum[SBLK];
__device__ int  g_sflag[SBLK];
__device__ int  g_batchi[NN];

// ---------------- helpers ----------------
__device__ __forceinline__ void red_f32(float* p, float v) {
    asm volatile("red.global.add.f32 [%0], %1;" :: "l"(p), "f"(v) : "memory");
}
__device__ __forceinline__ unsigned long long splat2(float w) {
    unsigned long long r;
    asm("mov.b64 %0, {%1, %1};" : "=l"(r) : "r"(__float_as_uint(w)));
    return r;
}
__device__ __forceinline__ unsigned long long pack2(float a, float b) {
    unsigned long long r;
    asm("mov.b64 %0, {%1, %2};" : "=l"(r) : "r"(__float_as_uint(a)), "r"(__float_as_uint(b)));
    return r;
}
__device__ __forceinline__ void unpack2(unsigned long long v, float& a, float& b) {
    unsigned lo, hi;
    asm("mov.b64 {%0, %1}, %2;" : "=r"(lo), "=r"(hi) : "l"(v));
    a = __uint_as_float(lo); b = __uint_as_float(hi);
}
__device__ __forceinline__ void fma_f32x2(unsigned long long& d,
                                          unsigned long long a,
                                          unsigned long long b) {
    asm("fma.rn.f32x2 %0, %1, %2, %0;" : "+l"(d) : "l"(a), "l"(b));
}
__device__ __forceinline__ unsigned long long add_f32x2(unsigned long long a,
                                                        unsigned long long b) {
    unsigned long long r;
    asm("add.rn.f32x2 %0, %1, %2;" : "=l"(r) : "l"(a), "l"(b));
    return r;
}

// ---------------- 1: fused weight-fold (blocks 0..56) + convert (rest) ----------------
__global__ __launch_bounds__(512) void k_prepconvert(
        const void* __restrict__ ei, const void* __restrict__ batch,
        const float* __restrict__ Wn, const float* __restrict__ bn,
        const float* __restrict__ We, const float* __restrict__ be,
        const float* __restrict__ Wm, const float* __restrict__ bm,
        const float* __restrict__ Wu, const float* __restrict__ bu) {
    const int t = threadIdx.x;
    const int b = blockIdx.x;

    if (b >= 57) {                     // ---- convert: indices + histogram + rank ----
        int i = (b - 57) * 512 + t;
        const int* ei32 = (const int*)ei;
        bool active = (i < 2*NE);
        int j = (i < NE) ? i : i - NE;
        int hw = active ? ei32[2*j + 1] : 0;
        unsigned m = __ballot_sync(0xffffffffu, active && (hw != 0));
        const bool f64 = (m == 0u);    // int64: all odd words zero
        if (active) {
            int v = f64 ? (int)((const long long*)ei)[i] : ei32[i];
            if (i < NE) {
                g_row[i] = v;
            } else {
                int r = atomicAdd(&g_deg[v], 1);
                g_col[i - NE]  = v;
                g_rank[i - NE] = r;
            }
        }
        if (i < NN) {
            g_batchi[i] = f64 ? (int)((const long long*)batch)[i] : ((const int*)batch)[i];
        }
        return;
    }

    // ---- prep: split-K weight folds ----
    __shared__ float swl[HID];
    __shared__ float sred[4][HID];
    __shared__ float sred4[4][4][HID];
    __shared__ float sbn[HID], sbe[HID];
    const int c = t & 127;
    const int q = t >> 7;

    if (b < 56) {
        const float* Wl;
        const float* Wr;
        float* out;
        int orow;
        if (b < 48) {
            int grp = b >> 4;
            orow = b & 15;
            Wl = Wn + orow*HID;
            if      (grp == 0) { Wr = Wm;           out = g_WA;  }
            else if (grp == 1) { Wr = Wm + HID*HID; out = g_WB;  }
            else               { Wr = Wu;           out = g_WU1; }
        } else {
            orow = b - 48;
            Wl = We + orow*HID;
            Wr = Wm + 2*HID*HID;
            out = g_WE2;
        }
        if (t < HID) swl[t] = Wl[t];
        __syncthreads();
        float a0 = 0.f, a1 = 0.f;
        const int k0 = 32*q;
        #pragma unroll
        for (int kk = 0; kk < 32; kk += 2) {
            a0 += swl[k0+kk]   * Wr[(k0+kk)*HID + c];
            a1 += swl[k0+kk+1] * Wr[(k0+kk+1)*HID + c];
        }
        sred[q][c] = a0 + a1;
        __syncthreads();
        if (q == 0)
            out[orow*HID + c] = (sred[0][c] + sred[1][c]) + (sred[2][c] + sred[3][c]);
    } else {
        if (t < HID) { sbn[t] = bn[t]; sbe[t] = be[t]; }
        __syncthreads();
        float p0 = 0.f, p1 = 0.f, p2 = 0.f, p3 = 0.f;
        const int k0 = 32*q;
        #pragma unroll
        for (int kk = 0; kk < 32; kk++) {
            int k = k0 + kk;
            float bnk = sbn[k];
            p0 += bnk    * Wm[k*HID + c];
            p1 += bnk    * Wm[(HID + k)*HID + c];
            p2 += sbe[k] * Wm[(2*HID + k)*HID + c];
            p3 += bnk    * Wu[k*HID + c];
        }
        sred4[q][0][c] = p0; sred4[q][1][c] = p1;
        sred4[q][2][c] = p2; sred4[q][3][c] = p3;
        __syncthreads();
        if (q == 0) {
            float b0 = sred4[0][0][c]+sred4[1][0][c]+sred4[2][0][c]+sred4[3][0][c];
            float b1 = sred4[0][1][c]+sred4[1][1][c]+sred4[2][1][c]+sred4[3][1][c];
            float b2 = sred4[0][2][c]+sred4[1][2][c]+sred4[2][2][c]+sred4[3][2][c];
            float u0 = sred4[0][3][c]+sred4[1][3][c]+sred4[2][3][c]+sred4[3][3][c];
            g_bconst[c] = bm[c] + b0 + b1 + b2;
            g_bup[c]    = bu[c] + u0;
        }
    }
}

// ---------------- 2: fused exclusive scan (decoupled lookback), clears g_deg ----------------
__global__ __launch_bounds__(1024) void k_scan() {
    __shared__ int swsum[32];
    __shared__ int soff;
    int t = threadIdx.x, b = blockIdx.x;
    int idx = b * 1024 + t;
    int lane = t & 31, warp = t >> 5;
    int d = (idx < NN) ? g_deg[idx] : 0;
    if (idx < NN) g_deg[idx] = 0;            // consume-and-clear for next call

    int v = d;
    #pragma unroll
    for (int o = 1; o < 32; o <<= 1) {
        int u = __shfl_up_sync(0xffffffffu, v, o);
        if (lane >= o) v += u;
    }
    if (lane == 31) swsum[warp] = v;
    __syncthreads();
    if (warp == 0) {
        int s = swsum[lane];
        #pragma unroll
        for (int o = 1; o < 32; o <<= 1) {
            int u = __shfl_up_sync(0xffffffffu, s, o);
            if (lane >= o) s += u;
        }
        swsum[lane] = s;
    }
    __syncthreads();
    int incl = v + ((warp > 0) ? swsum[warp - 1] : 0);

    if (t == 1023) {                          // publish block total
        g_bsum[b] = incl;
        __threadfence();
        atomicExch(&g_sflag[b], 1);
    }
    if (t < 32) {                             // lookback over predecessors
        int acc = 0;
        for (int j = t; j < b; j += 32) {
            while (atomicAdd(&g_sflag[j], 0) == 0) {}
            acc += atomicAdd(&g_bsum[j], 0);
        }
        #pragma unroll
        for (int o = 16; o > 0; o >>= 1) acc += __shfl_down_sync(0xffffffffu, acc, o);
        if (t == 0) soff = acc;
    }
    __syncthreads();
    if (idx < NN) g_ptr[idx] = (incl - d) + soff;
    if (b == 0 && t == 0) g_ptr[NN] = NE;     // degree sum is NE by construction
}

// ---------------- 3: fused node projections (blocks 0..NBN-1) + scatter (rest) ----------------
__global__ __launch_bounds__(256) void k_scatternode(const float* __restrict__ x) {
    const int t = threadIdx.x;
    const int b = blockIdx.x;

    if (b >= NBN) {                    // ---- scatter (pure stores) + clear sflag ----
        int i = (b - NBN) * 256 + t;
        if (i < NE) {
            int c = g_col[i];
            g_epack[g_ptr[c] + g_rank[i]] = make_int2(g_row[i], i);
        }
        if (i < SBLK) g_sflag[i] = 0;  // consume-and-clear for next call
        return;
    }

    // ---- node: pa/pb via channel-per-thread, broadcast LDS, f32x2 ----
    __shared__ __align__(16) float sxT[16][36];   // [i][n], 144B rows
    const int n0 = b * 32;
    #pragma unroll
    for (int r = 0; r < 2; r++) {
        int f = t + 256*r;             // 512 elements = 32 nodes x 16 feats
        int n = f >> 4, i = f & 15;
        int node = n0 + n;
        sxT[i][n] = (node < NN) ? x[(long long)node*16 + i] : 0.f;
    }
    __syncthreads();

    const int ch  = t & 127;
    const float* W   = (t >= 128) ? g_WB : g_WA;
    float*       OUT = (t >= 128) ? g_pb : g_pa;

    unsigned long long acc2[16];
    #pragma unroll
    for (int p = 0; p < 16; p++) acc2[p] = 0ULL;

    #pragma unroll
    for (int i = 0; i < 16; i++) {
        unsigned long long w2 = splat2(W[i*HID + ch]);
        const ulonglong2* srow = (const ulonglong2*)&sxT[i][0];
        #pragma unroll
        for (int qq = 0; qq < 8; qq++) {
            ulonglong2 a = srow[qq];   // broadcast (all lanes same addr)
            fma_f32x2(acc2[2*qq],   a.x, w2);
            fma_f32x2(acc2[2*qq+1], a.y, w2);
        }
    }
    #pragma unroll
    for (int p = 0; p < 16; p++) {
        float v0, v1;
        unpack2(acc2[p], v0, v1);
        int na = n0 + 2*p, nb2 = n0 + 2*p + 1;
        if (na  < NN) OUT[(long long)na *HID + ch] = v0;   // coalesced across ch
        if (nb2 < NN) OUT[(long long)nb2*HID + ch] = v1;
    }
}

// ---------------- 4: CSR aggregation — weights in registers, pipelined gathers ----------------
__global__ __launch_bounds__(256) void k_agg(const float* __restrict__ ea) {
    __shared__ float4 sbc[32];
    int t = threadIdx.x;
    int warp = t >> 5, lane = t & 31;

    unsigned long long wx[8], wy[8];   // WE2[j][4*lane..4*lane+3] per lane
    #pragma unroll
    for (int j = 0; j < 8; j++) {
        ulonglong2 w = ((const ulonglong2*)g_WE2)[j*32 + lane];
        wx[j] = w.x; wy[j] = w.y;
    }
    if (t < 32) sbc[t] = ((const float4*)g_bconst)[t];
    __syncthreads();

    int node = blockIdx.x * 8 + warp;
    if (node >= NN) return;
    int beg = g_ptr[node];
    int end = g_ptr[node + 1];

    float4 pbv = ((const float4*)g_pb)[node*32 + lane];
    float4 bc  = sbc[lane];
    unsigned long long bx0 = pack2(pbv.x + bc.x, pbv.y + bc.y);
    unsigned long long bx1 = pack2(pbv.z + bc.z, pbv.w + bc.w);

    float4 acc = {0.f, 0.f, 0.f, 0.f};
    int2 e1 = {0,0}, e2 = {0,0};
    ulonglong2 pav = {0ULL, 0ULL};
    float4 A = {0,0,0,0}, B = {0,0,0,0};
    if (beg < end)     e1 = g_epack[beg];
    if (beg + 1 < end) e2 = g_epack[beg + 1];
    if (beg < end) {
        pav = ((const ulonglong2*)g_pa)[e1.x*32 + lane];
        const float4* eap = (const float4*)(ea + (long long)e1.y*8);
        A = eap[0]; B = eap[1];
    }
    for (int p = beg; p < end; p++) {
        ulonglong2 pc = pav;
        float4 Ac = A, Bc = B;
        e1 = e2;
        if (p + 2 < end) e2 = g_epack[p + 2];
        if (p + 1 < end) {
            pav = ((const ulonglong2*)g_pa)[e1.x*32 + lane];
            const float4* eap = (const float4*)(ea + (long long)e1.y*8);
            A = eap[0]; B = eap[1];
        }
        unsigned long long m0 = add_f32x2(pc.x, bx0);
        unsigned long long m1 = add_f32x2(pc.y, bx1);
        float ej[8] = {Ac.x, Ac.y, Ac.z, Ac.w, Bc.x, Bc.y, Bc.z, Bc.w};
        #pragma unroll
        for (int j = 0; j < 8; j++) {
            unsigned long long ej2 = splat2(ej[j]);
            fma_f32x2(m0, ej2, wx[j]);
            fma_f32x2(m1, ej2, wy[j]);
        }
        float f0, f1, f2, f3;
        unpack2(m0, f0, f1);
        unpack2(m1, f2, f3);
        acc.x += fmaxf(f0, 0.f);
        acc.y += fmaxf(f1, 0.f);
        acc.z += fmaxf(f2, 0.f);
        acc.w += fmaxf(f3, 0.f);
    }
    float inv = 1.f / fmaxf((float)(end - beg), 1.f);
    acc.x *= inv; acc.y *= inv; acc.z *= inv; acc.w *= inv;
    ((float4*)g_agg)[node*32 + lane] = acc;
}

// ---------------- 5: node update + graph pooling ----------------
__global__ __launch_bounds__(128) void k_update(const float* __restrict__ x,
                                                const float* __restrict__ Wu) {
    __shared__ __align__(16) float saggT[HID][UNB + 4];
    __shared__ __align__(16) float sxT[16][UNB + 4];
    __shared__ int sbatch[UNB];
    int t  = threadIdx.x;                   // thread = channel c
    int n0 = blockIdx.x * UNB;

    if (t < UNB) {
        int node = n0 + t;
        sbatch[t] = (node < NN) ? g_batchi[node] : 0;
    }
    for (int n = 0; n < UNB; n++) {
        int node = n0 + n;
        saggT[t][n] = (node < NN) ? g_agg[node*HID + t] : 0.f;
    }
    for (int idx = t; idx < 16*UNB; idx += 128) {
        int n = idx & 31, i = idx >> 5;
        int node = n0 + n;
        sxT[i][n] = (node < NN) ? x[node*16 + i] : 0.f;
    }
    __syncthreads();

    const int c = t;
    unsigned long long acc2[UNB/2];
    #pragma unroll
    for (int p = 0; p < UNB/2; p++) acc2[p] = 0ULL;

    #pragma unroll
    for (int i = 0; i < 16; i++) {
        unsigned long long w2 = splat2(g_WU1[i*HID + c]);
        const ulonglong2* srow = (const ulonglong2*)&sxT[i][0];
        #pragma unroll
        for (int q = 0; q < UNB/4; q++) {
            ulonglong2 a = srow[q];
            fma_f32x2(acc2[2*q],   a.x, w2);
            fma_f32x2(acc2[2*q+1], a.y, w2);
        }
    }
    for (int k = 0; k < HID; k++) {
        unsigned long long w2 = splat2(Wu[(HID + k)*HID + c]);   // Wu_bot
        const ulonglong2* srow = (const ulonglong2*)&saggT[k][0];
        #pragma unroll
        for (int q = 0; q < UNB/4; q++) {
            ulonglong2 a = srow[q];
            fma_f32x2(acc2[2*q],   a.x, w2);
            fma_f32x2(acc2[2*q+1], a.y, w2);
        }
    }

    float bupv = g_bup[c];
    int   rep  = blockIdx.x & (REP - 1);
    float* gsbase = &g_gsum[rep*NGR*HID];
    int   cur = sbatch[0];
    float sum = 0.f;
    #pragma unroll
    for (int p = 0; p < UNB/2; p++) {
        float hv[2];
        unpack2(acc2[p], hv[0], hv[1]);
        #pragma unroll
        for (int q = 0; q < 2; q++) {
            int n = 2*p + q;
            int node = n0 + n;
            if (node < NN) {
                float h = fmaxf(hv[q] + bupv, 0.f);
                int b = sbatch[n];
                if (b != cur) {
                    red_f32(gsbase + cur*HID + c, sum);
                    cur = b; sum = 0.f;
                }
                sum += h;
            }
        }
    }
    red_f32(gsbase + cur*HID + c, sum);

    if (t < UNB) {
        int node = n0 + t;
        if (node < NN) red_f32(&g_gcnt[rep*NGR + sbatch[t]], 1.0f);
    }
}

// ---------------- 6: readout MLP, clears g_gsum/g_gcnt ----------------
__global__ __launch_bounds__(128) void k_final(const float* __restrict__ Wr1,
                                               const float* __restrict__ br1,
                                               const float* __restrict__ Wr2,
                                               const float* __restrict__ br2,
                                               float* __restrict__ out) {
    __shared__ float sg[HID];
    __shared__ float sred[4];
    int g = blockIdx.x, t = threadIdx.x;
    float s = 0.f;
    for (int r = 0; r < REP; r++) s += g_gsum[r*NGR*HID + g*HID + t];
    float gc = 0.f;
    for (int r = 0; r < REP; r++) gc += g_gcnt[r*NGR + g];
    sg[t] = s / fmaxf(gc, 1.f);
    __syncthreads();
    // consume-and-clear (this block owns graph g's slots)
    for (int r = 0; r < REP; r++) g_gsum[r*NGR*HID + g*HID + t] = 0.f;
    if (t == 0) for (int r = 0; r < REP; r++) g_gcnt[r*NGR + g] = 0.f;

    float acc = br1[t];
    for (int k = 0; k < HID; k++) acc += sg[k] * Wr1[k*HID + t];
    acc = fmaxf(acc, 0.f);
    float v = acc * Wr2[t];
    #pragma unroll
    for (int o = 16; o > 0; o >>= 1) v += __shfl_down_sync(0xffffffffu, v, o);
    if ((t & 31) == 0) sred[t >> 5] = v;
    __syncthreads();
    if (t == 0) out[g] = sred[0] + sred[1] + sred[2] + sred[3] + br2[0];
}

// ---------------- launch ----------------
extern "C" void kernel_launch(void* const* d_in, const int* in_sizes, int n_in,
                              void* d_out, int out_size) {
    const float* x     = (const float*)d_in[0];
    const float* ea    = (const float*)d_in[1];
    const void*  ei    = d_in[2];
    const void*  batch = d_in[3];
    const float* Wn  = (const float*)d_in[4];
    const float* bn  = (const float*)d_in[5];
    const float* We  = (const float*)d_in[6];
    const float* be  = (const float*)d_in[7];
    const float* Wm  = (const float*)d_in[8];
    const float* bm  = (const float*)d_in[9];
    const float* Wu  = (const float*)d_in[10];
    const float* bu  = (const float*)d_in[11];
    const float* Wr1 = (const float*)d_in[12];
    const float* br1 = (const float*)d_in[13];
    const float* Wr2 = (const float*)d_in[14];
    const float* br2 = (const float*)d_in[15];
    float* out = (float*)d_out;

    k_prepconvert <<<57 + NBC, 512>>>(ei, batch, Wn, bn, We, be, Wm, bm, Wu, bu);
    k_scan        <<<SBLK, 1024>>>();
    k_scatternode <<<NBN + NBS, 256>>>(x);
    k_agg         <<<(NN + 7)/8, 256>>>(ea);     // launch #4 -> profiled
    k_update      <<<(NN + UNB - 1)/UNB, 128>>>(x, Wu);
    k_final       <<<NGR, 128>>>(Wr1, br1, Wr2, br2, out);
}